// round 15
// baseline (speedup 1.0000x reference)
#include <cuda_runtime.h>
#include <cuda_fp16.h>
#include <cstdint>
#include <math.h>

#define B_    4096
#define OBS_  4096
#define ENC_  1024
#define LAT_  512
#define L3_   1536
#define ACT_  3
#define NMAX_ 8

// ---------------- scratch ----------------
__device__ __half g_enc[B_ * ENC_];
__device__ __half g_h0 [B_ * LAT_];
__device__ __half g_h1 [B_ * LAT_];
__device__ float  g_gi [B_ * NMAX_ * L3_];      // sliced layout: padoff[t] + sorted row
__device__ __half g_obs_h [B_ * OBS_];
__device__ __half g_nb_c  [B_ * NMAX_ * LAT_];
__device__ __half g_Wds_h [ENC_ * OBS_];
__device__ __half g_Wpol_h[LAT_ * ENC_];
__device__ __half g_Wih_h [L3_ * LAT_];
__device__ __half g_Whp   [L3_ * LAT_];
__device__ float  g_bhp   [L3_];
__device__ int    g_perm  [B_];
__device__ int    g_order [B_];
__device__ int    g_cnt_s [B_];
__device__ int    g_active[NMAX_];
__device__ int    g_padoff[NMAX_];

// ---------------- fp32 -> fp16 conversion ----------------
__global__ __launch_bounds__(256)
void to_half_k(const float* __restrict__ in, __half* __restrict__ out, int n4)
{
    int i = blockIdx.x * 256 + threadIdx.x;
    if (i >= n4) return;
    float4 v = ((const float4*)in)[i];
    ((__half2*)out)[2 * i]     = __floats2half2_rn(v.x, v.y);
    ((__half2*)out)[2 * i + 1] = __floats2half2_rn(v.z, v.w);
}

// ------- merged prep: counting sort (desc) + tables + slice offsets (1 CTA) --
__global__ __launch_bounds__(1024)
void prep_all(const int* __restrict__ counts, int* __restrict__ perm,
              int* __restrict__ order, int* __restrict__ cnt_s,
              int* __restrict__ active, int* __restrict__ padoff)
{
    __shared__ int hist[9][1024];
    const int tid = threadIdx.x;

    int c[4];
    #pragma unroll
    for (int i = 0; i < 4; i++) c[i] = counts[tid * 4 + i];
    int loc[9];
    #pragma unroll
    for (int b = 0; b < 9; b++) loc[b] = 0;
    #pragma unroll
    for (int i = 0; i < 4; i++) loc[c[i]]++;
    #pragma unroll
    for (int b = 0; b < 9; b++) hist[b][tid] = loc[b];
    __syncthreads();

    for (int o = 1; o < 1024; o <<= 1) {
        int vb[9];
        #pragma unroll
        for (int b = 0; b < 9; b++) vb[b] = (tid >= o) ? hist[b][tid - o] : 0;
        __syncthreads();
        #pragma unroll
        for (int b = 0; b < 9; b++) hist[b][tid] += vb[b];
        __syncthreads();
    }

    int total[9], start[9];
    #pragma unroll
    for (int b = 0; b < 9; b++) total[b] = hist[b][1023];
    int a = 0;
    for (int b = 8; b >= 0; b--) { start[b] = a; a += total[b]; }
    int exb[9];
    #pragma unroll
    for (int b = 0; b < 9; b++) exb[b] = hist[b][tid] - loc[b];
    #pragma unroll
    for (int i = 0; i < 4; i++) {
        int b = tid * 4 + i, cc = c[i];
        int pos = start[cc] + exb[cc]++;
        perm[b] = pos;
        order[pos] = b;
    }
    if (tid < NMAX_) active[tid] = start[tid];
    if (tid == 0) {
        int po = 0;
        #pragma unroll
        for (int t = 0; t < NMAX_; t++) {
            padoff[t] = po;
            po += ((start[t] + 127) >> 7) << 7;
        }
    }
    __syncthreads();

    #pragma unroll
    for (int i = 0; i < 4; i++) {
        int p = tid * 4 + i;
        cnt_s[p] = counts[order[p]];
    }
}

// ------- gather neighbors into sliced sorted layout + fp16 convert ----------
__global__ __launch_bounds__(256)
void gather_nb(const float* __restrict__ nb, const int* __restrict__ counts,
               const int* __restrict__ perm, const int* __restrict__ padoff,
               __half* __restrict__ out)
{
    const int b = blockIdx.x;
    const int w = threadIdx.x >> 5;
    const int lane = threadIdx.x & 31;
    if (w >= counts[b]) return;
    const float* src = nb + ((size_t)b * NMAX_ + w) * LAT_;
    __half* dst = out + (size_t)(padoff[w] + perm[b]) * LAT_;
    #pragma unroll
    for (int it = 0; it < 4; it++) {
        float4 v = *(const float4*)(src + it * 128 + lane * 4);
        *(__half2*)(dst + it * 128 + lane * 4)     = __floats2half2_rn(v.x, v.y);
        *(__half2*)(dst + it * 128 + lane * 4 + 2) = __floats2half2_rn(v.z, v.w);
    }
}

// ---------------- permute W_hh/b_hh gate-interleaved -------------
__global__ __launch_bounds__(256)
void permute_whh(const float* __restrict__ Whh, const float* __restrict__ bhh,
                 __half* __restrict__ Whp, float* __restrict__ bhp)
{
    const int m = blockIdx.x * 8 + (threadIdx.x >> 5);
    const int lane = threadIdx.x & 31;
    const int gate = m >> 9, j = m & 511;
    const int mp = ((j >> 3) * 3 + gate) * 8 + (j & 7);
    const float* src = Whh + (size_t)m * LAT_;
    __half* dst = Whp + (size_t)mp * LAT_;
    #pragma unroll
    for (int it = 0; it < 4; it++) {
        float4 v = *(const float4*)(src + it * 128 + lane * 4);
        *(__half2*)(dst + it * 128 + lane * 4)     = __floats2half2_rn(v.x, v.y);
        *(__half2*)(dst + it * 128 + lane * 4 + 2) = __floats2half2_rn(v.z, v.w);
    }
    if (lane == 0) bhp[mp] = bhh[m];
}

// ====== common MMA macros ======
#define KCH   64

#define CP_ASYNC16(dst, src) \
    asm volatile("cp.async.cg.shared.global [%0], [%1], 16;" :: "r"(dst), "l"(src))
#define CP_COMMIT()  asm volatile("cp.async.commit_group;" ::: "memory")
#define CP_WAIT1()   asm volatile("cp.async.wait_group 1;" ::: "memory")
#define CP_WAIT0()   asm volatile("cp.async.wait_group 0;" ::: "memory")
#define LDSM_X4(r0, r1, r2, r3, addr) \
    asm volatile("ldmatrix.sync.aligned.m8n8.x4.shared.b16 {%0,%1,%2,%3}, [%4];" \
                 : "=r"(r0), "=r"(r1), "=r"(r2), "=r"(r3) : "r"(addr))
#define HMMA16(acc, a, b) \
    asm volatile("mma.sync.aligned.m16n8k16.row.col.f32.f16.f16.f32 " \
                 "{%0, %1, %2, %3}, {%4, %5, %6, %7}, {%8, %9}, {%0, %1, %2, %3};" \
                 : "+f"((acc)[0]), "+f"((acc)[1]), "+f"((acc)[2]), "+f"((acc)[3]) \
                 : "r"((a)[0]), "r"((a)[1]), "r"((a)[2]), "r"((a)[3]), \
                   "r"((b)[0]), "r"((b)[1]))

// ====== fp16 mma.sync GEMM, BM x 128 CTA tile (enc / pol), 3-stage ======
template<int BM, int PERM>
__global__ __launch_bounds__(256, 2)
void gemm_h(const __half* __restrict__ A, const __half* __restrict__ W,
            const float* __restrict__ bias, __half* __restrict__ C,
            int N, int K, const int* __restrict__ perm)
{
    constexpr int A_TILE = BM * 144;
    constexpr int B_TILE = 128 * 144;
    constexpr int STAGE  = A_TILE + B_TILE;
    constexpr int MI     = BM / 32;

    extern __shared__ uint32_t sm[];
    const uint32_t sbase = (uint32_t)__cvta_generic_to_shared(sm);

    const int tid  = threadIdx.x;
    const int wid  = tid >> 5;
    const int lane = tid & 31;
    const int g    = lane >> 2;
    const int t    = lane & 3;
    const int wm   = wid & 1;
    const int wn   = wid >> 1;

    const int n0 = blockIdx.x * 128;
    const int m0 = blockIdx.y * BM;
    const __half* Ab = A + (size_t)m0 * K;
    const __half* Wb = W + (size_t)n0 * K;
    const int NC = K / KCH;

    const int row_ld = tid >> 3;
    const int kq_ld  = tid & 7;

    auto issue_stage = [&](int c, int s) {
        const int k0 = c * KCH;
        uint32_t a_st = sbase + (uint32_t)(s * STAGE);
        uint32_t b_st = a_st + (uint32_t)A_TILE;
        #pragma unroll
        for (int i = 0; i < BM / 32; i++) {
            int row = row_ld + i * 32;
            CP_ASYNC16(a_st + (uint32_t)(row * 144 + kq_ld * 16),
                       Ab + (size_t)row * K + k0 + kq_ld * 8);
        }
        #pragma unroll
        for (int i = 0; i < 4; i++) {
            int row = row_ld + i * 32;
            CP_ASYNC16(b_st + (uint32_t)(row * 144 + kq_ld * 16),
                       Wb + (size_t)row * K + k0 + kq_ld * 8);
        }
    };

    float acc[MI][4][4];
    #pragma unroll
    for (int i = 0; i < MI; i++)
        #pragma unroll
        for (int j = 0; j < 4; j++)
            #pragma unroll
            for (int r = 0; r < 4; r++) acc[i][j][r] = 0.f;

    issue_stage(0, 0); CP_COMMIT();
    if (NC > 1) issue_stage(1, 1);
    CP_COMMIT();

    const int lrow = lane & 15;
    const int lcol = (lane >> 4) * 16;

    for (int c = 0; c < NC; c++) {
        const int s = c % 3;
        CP_WAIT1();
        __syncthreads();
        if (c + 2 < NC) issue_stage(c + 2, (c + 2) % 3);
        CP_COMMIT();

        const uint32_t a_st = sbase + (uint32_t)(s * STAGE);
        const uint32_t b_st = a_st + (uint32_t)A_TILE;

        #pragma unroll
        for (int kk = 0; kk < 4; kk++) {
            uint32_t af[MI][4], bf[4][2];
            #pragma unroll
            for (int i = 0; i < MI; i++) {
                int row = wm * (BM / 2) + i * 16 + lrow;
                LDSM_X4(af[i][0], af[i][1], af[i][2], af[i][3],
                        a_st + (uint32_t)(row * 144 + kk * 32 + lcol));
            }
            #pragma unroll
            for (int j2 = 0; j2 < 2; j2++) {
                int row = wn * 32 + j2 * 16 + lrow;
                uint32_t r0, r1, r2, r3;
                LDSM_X4(r0, r1, r2, r3, b_st + (uint32_t)(row * 144 + kk * 32 + lcol));
                bf[j2 * 2][0] = r0; bf[j2 * 2 + 1][0] = r1;
                bf[j2 * 2][1] = r2; bf[j2 * 2 + 1][1] = r3;
            }
            #pragma unroll
            for (int i = 0; i < MI; i++)
                #pragma unroll
                for (int j = 0; j < 4; j++)
                    HMMA16(acc[i][j], af[i], bf[j]);
        }
    }

    #pragma unroll
    for (int i = 0; i < MI; i++) {
        const int row = m0 + wm * (BM / 2) + i * 16 + g;
        const int orow0 = PERM ? perm[row] : row;
        const int orow1 = PERM ? perm[row + 8] : row + 8;
        #pragma unroll
        for (int j = 0; j < 4; j++) {
            const int col = n0 + wn * 32 + j * 8 + 2 * t;
            const float b0 = bias[col], b1 = bias[col + 1];
            float x0 = fmaxf(acc[i][j][0] + b0, 0.f);
            float x1 = fmaxf(acc[i][j][1] + b1, 0.f);
            float x2 = fmaxf(acc[i][j][2] + b0, 0.f);
            float x3 = fmaxf(acc[i][j][3] + b1, 0.f);
            *(__half2*)(C + (size_t)orow0 * N + col) = __floats2half2_rn(x0, x1);
            *(__half2*)(C + (size_t)orow1 * N + col) = __floats2half2_rn(x2, x3);
        }
    }
}

#define SMEM_128 (3 * (128 * 144 + 128 * 144))
#define SMEM_64  (3 * (64 * 144 + 128 * 144))

// ====== gi slice GEMM: 2-STAGE (73.7 KB) for co-residency ======
#define GI_STAGE (2 * 128 * 144)
#define GI_SMEM  (2 * GI_STAGE)       // 73728

__global__ __launch_bounds__(256, 2)
void gemm_gi(const __half* __restrict__ nb, const __half* __restrict__ W,
             const float* __restrict__ bias, float* __restrict__ gi,
             const int* __restrict__ active, const int* __restrict__ padoff, int ts)
{
    const int nact = active[ts];
    if ((int)blockIdx.y * 128 >= nact) return;
    const size_t po = (size_t)padoff[ts];
    const __half* A = nb + po * LAT_;
    float* C = gi + po * L3_;
    const int K = LAT_, N = L3_;

    extern __shared__ uint32_t sm[];
    const uint32_t sbase = (uint32_t)__cvta_generic_to_shared(sm);

    const int tid  = threadIdx.x;
    const int wid  = tid >> 5;
    const int lane = tid & 31;
    const int g    = lane >> 2;
    const int t    = lane & 3;
    const int wm   = wid & 1;
    const int wn   = wid >> 1;

    const int n0 = blockIdx.x * 128;
    const int m0 = blockIdx.y * 128;
    const __half* Ab = A + (size_t)m0 * K;
    const __half* Wb = W + (size_t)n0 * K;
    const int NC = K / KCH;   // 8

    const int row_ld = tid >> 3;
    const int kq_ld  = tid & 7;

    auto issue_stage = [&](int c, int s) {
        const int k0 = c * KCH;
        uint32_t a_st = sbase + (uint32_t)(s * GI_STAGE);
        uint32_t b_st = a_st + (uint32_t)(128 * 144);
        #pragma unroll
        for (int i = 0; i < 4; i++) {
            int row = row_ld + i * 32;
            uint32_t off = (uint32_t)(row * 144 + kq_ld * 16);
            CP_ASYNC16(a_st + off, Ab + (size_t)row * K + k0 + kq_ld * 8);
            CP_ASYNC16(b_st + off, Wb + (size_t)row * K + k0 + kq_ld * 8);
        }
    };

    float acc[4][4][4];
    #pragma unroll
    for (int i = 0; i < 4; i++)
        #pragma unroll
        for (int j = 0; j < 4; j++)
            #pragma unroll
            for (int r = 0; r < 4; r++) acc[i][j][r] = 0.f;

    issue_stage(0, 0); CP_COMMIT();

    const int lrow = lane & 15;
    const int lcol = (lane >> 4) * 16;

    for (int c = 0; c < NC; c++) {
        const int s = c & 1;
        if (c + 1 < NC) { issue_stage(c + 1, s ^ 1); CP_COMMIT(); CP_WAIT1(); }
        else            { CP_WAIT0(); }
        __syncthreads();

        const uint32_t a_st = sbase + (uint32_t)(s * GI_STAGE);
        const uint32_t b_st = a_st + (uint32_t)(128 * 144);

        #pragma unroll
        for (int kk = 0; kk < 4; kk++) {
            uint32_t af[4][4], bf[4][2];
            #pragma unroll
            for (int i = 0; i < 4; i++) {
                int row = wm * 64 + i * 16 + lrow;
                LDSM_X4(af[i][0], af[i][1], af[i][2], af[i][3],
                        a_st + (uint32_t)(row * 144 + kk * 32 + lcol));
            }
            #pragma unroll
            for (int j2 = 0; j2 < 2; j2++) {
                int row = wn * 32 + j2 * 16 + lrow;
                uint32_t r0, r1, r2, r3;
                LDSM_X4(r0, r1, r2, r3, b_st + (uint32_t)(row * 144 + kk * 32 + lcol));
                bf[j2 * 2][0] = r0; bf[j2 * 2 + 1][0] = r1;
                bf[j2 * 2][1] = r2; bf[j2 * 2 + 1][1] = r3;
            }
            #pragma unroll
            for (int i = 0; i < 4; i++)
                #pragma unroll
                for (int j = 0; j < 4; j++)
                    HMMA16(acc[i][j], af[i], bf[j]);
        }
        __syncthreads();
    }

    #pragma unroll
    for (int i = 0; i < 4; i++) {
        const int row = m0 + wm * 64 + i * 16 + g;
        #pragma unroll
        for (int j = 0; j < 4; j++) {
            const int col = n0 + wn * 32 + j * 8 + 2 * t;
            const float b0 = bias[col], b1 = bias[col + 1];
            float2 v0 = { acc[i][j][0] + b0, acc[i][j][1] + b1 };
            float2 v1 = { acc[i][j][2] + b0, acc[i][j][3] + b1 };
            *(float2*)(C + (size_t)row * N + col)       = v0;
            *(float2*)(C + (size_t)(row + 8) * N + col) = v1;
        }
    }
}

// ====== fused GRU step: 128 x 96 tile, 2-STAGE (64.5 KB), 2 CTAs/SM ======
#define G2_AT (128 * 144)
#define G2_BT (96 * 144)
#define G2_STAGE (G2_AT + G2_BT)
#define G2_SMEM (2 * G2_STAGE)        // 64512

__device__ __forceinline__ float sigmoidf_(float x) { return 1.f / (1.f + expf(-x)); }

__global__ __launch_bounds__(256, 2)
void gru_step(const __half* __restrict__ hin, const __half* __restrict__ Whp,
              const float* __restrict__ bhp, const float* __restrict__ gi,
              const int* __restrict__ cnt_s, const int* __restrict__ padoff,
              const int* __restrict__ active, __half* __restrict__ hout, int tstep)
{
    const int m0 = blockIdx.y * 128;
    const int bx = blockIdx.x;
    const int tid = threadIdx.x;
    if (m0 >= active[tstep]) return;

    extern __shared__ uint32_t sm[];
    const uint32_t sbase = (uint32_t)__cvta_generic_to_shared(sm);
    const int wid = tid >> 5, lane = tid & 31;
    const int g = lane >> 2, t4 = lane & 3;
    const int wm = wid & 3;
    const int wn = wid >> 2;

    const __half* Ab = hin + (size_t)m0 * LAT_;
    const __half* Bb = Whp + (size_t)bx * 96 * LAT_;
    const size_t po = (size_t)padoff[tstep];

    const int row_ld = tid >> 3;
    const int kq_ld  = tid & 7;

    auto issue = [&](int c, int s) {
        const int k0 = c * 64;
        uint32_t ast = sbase + (uint32_t)(s * G2_STAGE);
        uint32_t bst = ast + G2_AT;
        #pragma unroll
        for (int i = 0; i < 4; i++) {
            int row = row_ld + i * 32;
            CP_ASYNC16(ast + (uint32_t)(row * 144 + kq_ld * 16),
                       Ab + (size_t)row * LAT_ + k0 + kq_ld * 8);
        }
        #pragma unroll
        for (int i = 0; i < 3; i++) {
            int row = row_ld + i * 32;
            CP_ASYNC16(bst + (uint32_t)(row * 144 + kq_ld * 16),
                       Bb + (size_t)row * LAT_ + k0 + kq_ld * 8);
        }
    };

    float acc[2][6][4];
    #pragma unroll
    for (int i = 0; i < 2; i++)
        #pragma unroll
        for (int j = 0; j < 6; j++)
            #pragma unroll
            for (int r = 0; r < 4; r++) acc[i][j][r] = 0.f;

    issue(0, 0); CP_COMMIT();

    const int lrow = lane & 15;
    const int lcol = (lane >> 4) * 16;

    for (int c = 0; c < 8; c++) {
        const int s = c & 1;
        if (c + 1 < 8) { issue(c + 1, s ^ 1); CP_COMMIT(); CP_WAIT1(); }
        else           { CP_WAIT0(); }
        __syncthreads();

        const uint32_t ast = sbase + (uint32_t)(s * G2_STAGE);
        const uint32_t bst = ast + G2_AT;

        #pragma unroll
        for (int kk = 0; kk < 4; kk++) {
            uint32_t af[2][4], bf[6][2];
            #pragma unroll
            for (int i = 0; i < 2; i++) {
                int row = wm * 32 + i * 16 + lrow;
                LDSM_X4(af[i][0], af[i][1], af[i][2], af[i][3],
                        ast + (uint32_t)(row * 144 + kk * 32 + lcol));
            }
            #pragma unroll
            for (int j2 = 0; j2 < 3; j2++) {
                int row = wn * 48 + j2 * 16 + lrow;
                uint32_t r0, r1, r2, r3;
                LDSM_X4(r0, r1, r2, r3, bst + (uint32_t)(row * 144 + kk * 32 + lcol));
                bf[j2 * 2][0] = r0; bf[j2 * 2 + 1][0] = r1;
                bf[j2 * 2][1] = r2; bf[j2 * 2 + 1][1] = r3;
            }
            #pragma unroll
            for (int i = 0; i < 2; i++)
                #pragma unroll
                for (int j = 0; j < 6; j++)
                    HMMA16(acc[i][j], af[i], bf[j]);
        }
        __syncthreads();
    }

    #pragma unroll
    for (int i = 0; i < 2; i++) {
        #pragma unroll
        for (int rh = 0; rh < 2; rh++) {
            const int row = m0 + wm * 32 + i * 16 + g + rh * 8;
            if (tstep >= cnt_s[row]) continue;
            const size_t girow = (po + row) * L3_;
            #pragma unroll
            for (int u = 0; u < 2; u++) {
                const int j0 = bx * 32 + (wn * 2 + u) * 8 + 2 * t4;
                const int cb = bx * 96 + wn * 48 + u * 24 + 2 * t4;
                const float ghr0 = acc[i][3*u  ][2*rh]   + bhp[cb];
                const float ghr1 = acc[i][3*u  ][2*rh+1] + bhp[cb + 1];
                const float ghz0 = acc[i][3*u+1][2*rh]   + bhp[cb + 8];
                const float ghz1 = acc[i][3*u+1][2*rh+1] + bhp[cb + 9];
                const float ghn0 = acc[i][3*u+2][2*rh]   + bhp[cb + 16];
                const float ghn1 = acc[i][3*u+2][2*rh+1] + bhp[cb + 17];
                __half2 hold = *(const __half2*)(hin + (size_t)row * LAT_ + j0);
                float h0 = __low2float(hold), h1 = __high2float(hold);
                float2 gir = *(const float2*)(gi + girow + j0);
                float2 giz = *(const float2*)(gi + girow + 512 + j0);
                float2 gin = *(const float2*)(gi + girow + 1024 + j0);
                float r0 = sigmoidf_(gir.x + ghr0);
                float r1 = sigmoidf_(gir.y + ghr1);
                float z0 = sigmoidf_(giz.x + ghz0);
                float z1 = sigmoidf_(giz.y + ghz1);
                float n0 = tanhf(gin.x + r0 * ghn0);
                float n1 = tanhf(gin.y + r1 * ghn1);
                h0 = (1.f - z0) * n0 + z0 * h0;
                h1 = (1.f - z1) * n1 + z1 * h1;
                *(__half2*)(hout + (size_t)row * LAT_ + j0) = __floats2half2_rn(h0, h1);
            }
        }
    }
}

// ---------------- value head ----------------
__global__ __launch_bounds__(256)
void vnet_kernel(const __half* __restrict__ enc, const float* __restrict__ Wv,
                 const float* __restrict__ bv, float* __restrict__ out)
{
    __shared__ float red[8];
    const int b = blockIdx.x;
    float s = 0.f;
    for (int k = threadIdx.x; k < ENC_; k += 256)
        s = fmaf(__half2float(enc[(size_t)b * ENC_ + k]), Wv[k], s);
    #pragma unroll
    for (int o = 16; o > 0; o >>= 1) s += __shfl_down_sync(0xffffffff, s, o);
    if ((threadIdx.x & 31) == 0) red[threadIdx.x >> 5] = s;
    __syncthreads();
    if (threadIdx.x == 0) {
        float tot = 0.f;
        #pragma unroll
        for (int w = 0; w < 8; w++) tot += red[w];
        out[b] = tanhf(tot + bv[0]);
    }
}

// ---------------- probs head (per-row buffer parity select) ----------------
__global__ __launch_bounds__(256)
void probs_kernel(const __half* __restrict__ h0, const __half* __restrict__ h1,
                  const int* __restrict__ perm, const int* __restrict__ cnt_s,
                  const float* __restrict__ Wpr, const float* __restrict__ bpr,
                  float* __restrict__ out)
{
    __shared__ float Ws[ACT_][LAT_];
    for (int i = threadIdx.x; i < ACT_ * LAT_; i += 256)
        Ws[i / LAT_][i % LAT_] = Wpr[i];
    __syncthreads();

    const int warp = threadIdx.x >> 5;
    const int lane = threadIdx.x & 31;
    const int b = blockIdx.x * 8 + warp;

    const int p = perm[b];
    const __half* hb = ((cnt_s[p] & 1) ? h1 : h0) + (size_t)p * LAT_;

    float a0 = 0.f, a1 = 0.f, a2 = 0.f;
    for (int k = lane; k < LAT_; k += 32) {
        float hv = __half2float(hb[k]);
        a0 = fmaf(hv, Ws[0][k], a0);
        a1 = fmaf(hv, Ws[1][k], a1);
        a2 = fmaf(hv, Ws[2][k], a2);
    }
    #pragma unroll
    for (int o = 16; o > 0; o >>= 1) {
        a0 += __shfl_down_sync(0xffffffff, a0, o);
        a1 += __shfl_down_sync(0xffffffff, a1, o);
        a2 += __shfl_down_sync(0xffffffff, a2, o);
    }
    if (lane == 0) {
        float l0 = fmaxf(a0 + bpr[0], 0.f);
        float l1 = fmaxf(a1 + bpr[1], 0.f);
        float l2 = fmaxf(a2 + bpr[2], 0.f);
        float m = fmaxf(l0, fmaxf(l1, l2));
        float e0 = expf(l0 - m), e1 = expf(l1 - m), e2 = expf(l2 - m);
        float inv = 1.f / (e0 + e1 + e2);
        out[(size_t)b * ACT_ + 0] = e0 * inv;
        out[(size_t)b * ACT_ + 1] = e1 * inv;
        out[(size_t)b * ACT_ + 2] = e2 * inv;
    }
}

// ---------------- launch ----------------
static inline void half_pass(const float* in, __half* out, size_t n, cudaStream_t s = 0) {
    int n4 = (int)(n / 4);
    to_half_k<<<(n4 + 255) / 256, 256, 0, s>>>(in, out, n4);
}

extern "C" void kernel_launch(void* const* d_in, const int* in_sizes, int n_in,
                              void* d_out, int out_size)
{
    static cudaStream_t s2 = [](){ cudaStream_t s;
        cudaStreamCreateWithFlags(&s, cudaStreamNonBlocking); return s; }();
    static cudaStream_t s3 = [](){ cudaStream_t s;
        cudaStreamCreateWithFlags(&s, cudaStreamNonBlocking); return s; }();
    static cudaEvent_t evA = [](){ cudaEvent_t e;
        cudaEventCreateWithFlags(&e, cudaEventDisableTiming); return e; }();
    static cudaEvent_t evE = [](){ cudaEvent_t e;
        cudaEventCreateWithFlags(&e, cudaEventDisableTiming); return e; }();
    static cudaEvent_t evP = [](){ cudaEvent_t e;
        cudaEventCreateWithFlags(&e, cudaEventDisableTiming); return e; }();
    static cudaEvent_t evV = [](){ cudaEvent_t e;
        cudaEventCreateWithFlags(&e, cudaEventDisableTiming); return e; }();
    static cudaEvent_t gEv[NMAX_];
    static bool evInit = [](){
        for (int i = 0; i < NMAX_; i++)
            cudaEventCreateWithFlags(&gEv[i], cudaEventDisableTiming);
        return true; }();
    (void)evInit;

    const float* observation = (const float*)d_in[0];
    const float* neighbors   = (const float*)d_in[1];
    const int*   counts      = (const int*)  d_in[2];
    const float* W_ds  = (const float*)d_in[3];
    const float* b_ds  = (const float*)d_in[4];
    const float* W_pol = (const float*)d_in[5];
    const float* b_pol = (const float*)d_in[6];
    const float* W_v   = (const float*)d_in[7];
    const float* b_v   = (const float*)d_in[8];
    const float* W_ih  = (const float*)d_in[9];
    const float* b_ih  = (const float*)d_in[10];
    const float* W_hh  = (const float*)d_in[11];
    const float* b_hh  = (const float*)d_in[12];
    const float* W_pr  = (const float*)d_in[13];
    const float* b_pr  = (const float*)d_in[14];

    float* out_probs = (float*)d_out;
    float* out_vals  = (float*)d_out + (size_t)B_ * ACT_;

    __half *enc, *h0, *h1, *obs_h, *nb_c, *Wds_h, *Wpol_h, *Wih_h, *Whp;
    float *gi, *bhp;
    int *perm, *order, *cnt_s, *active, *padoff;
    cudaGetSymbolAddress((void**)&enc,   g_enc);
    cudaGetSymbolAddress((void**)&h0,    g_h0);
    cudaGetSymbolAddress((void**)&h1,    g_h1);
    cudaGetSymbolAddress((void**)&gi,    g_gi);
    cudaGetSymbolAddress((void**)&obs_h, g_obs_h);
    cudaGetSymbolAddress((void**)&nb_c,  g_nb_c);
    cudaGetSymbolAddress((void**)&Wds_h, g_Wds_h);
    cudaGetSymbolAddress((void**)&Wpol_h,g_Wpol_h);
    cudaGetSymbolAddress((void**)&Wih_h, g_Wih_h);
    cudaGetSymbolAddress((void**)&Whp,   g_Whp);
    cudaGetSymbolAddress((void**)&bhp,   g_bhp);
    cudaGetSymbolAddress((void**)&perm,  g_perm);
    cudaGetSymbolAddress((void**)&order, g_order);
    cudaGetSymbolAddress((void**)&cnt_s, g_cnt_s);
    cudaGetSymbolAddress((void**)&active,g_active);
    cudaGetSymbolAddress((void**)&padoff,g_padoff);

    cudaFuncSetAttribute(gemm_h<128,0>, cudaFuncAttributeMaxDynamicSharedMemorySize, SMEM_128);
    cudaFuncSetAttribute(gemm_h<64,1>,  cudaFuncAttributeMaxDynamicSharedMemorySize, SMEM_64);
    cudaFuncSetAttribute(gemm_gi, cudaFuncAttributeMaxDynamicSharedMemorySize, GI_SMEM);
    cudaFuncSetAttribute(gru_step, cudaFuncAttributeMaxDynamicSharedMemorySize, G2_SMEM);

    // main: enc dependencies
    half_pass(observation, obs_h, (size_t)B_ * OBS_);
    half_pass(W_ds, Wds_h, (size_t)ENC_ * OBS_);

    // fork s2 into the capture
    cudaEventRecord(evA, 0);
    cudaStreamWaitEvent(s2, evA, 0);

    // main: enc GEMM
    gemm_h<128,0><<<dim3(ENC_ / 128, B_ / 128), 256, SMEM_128>>>(obs_h, Wds_h, b_ds, enc, ENC_, OBS_, nullptr);
    cudaEventRecord(evE, 0);

    // s3: vnet (off critical path; needs enc)
    cudaStreamWaitEvent(s3, evE, 0);
    vnet_kernel<<<B_, 256, 0, s3>>>(enc, W_v, b_v, out_vals);
    cudaEventRecord(evV, s3);

    // s2: prep chain (overlaps enc)
    prep_all<<<1, 1024, 0, s2>>>(counts, perm, order, cnt_s, active, padoff);
    gather_nb<<<B_, 256, 0, s2>>>(neighbors, counts, perm, padoff, nb_c);
    permute_whh<<<L3_ / 8, 256, 0, s2>>>(W_hh, b_hh, Whp, bhp);
    half_pass(W_ih, Wih_h, (size_t)L3_ * LAT_, s2);
    half_pass(W_pol, Wpol_h, (size_t)LAT_ * ENC_, s2);
    cudaEventRecord(evP, s2);

    // s2: gi slice GEMMs (2-stage smem -> co-resident with enc/pol/GRU)
    for (int t = 0; t < NMAX_; t++) {
        gemm_gi<<<dim3(L3_ / 128, 32), 256, GI_SMEM, s2>>>(nb_c, Wih_h, b_ih, gi, active, padoff, t);
        cudaEventRecord(gEv[t], s2);
    }

    // main: pol (needs evP: perm, Wpol)
    cudaStreamWaitEvent(0, evP, 0);
    gemm_h<64,1><<<dim3(LAT_ / 128, B_ / 64), 256, SMEM_64>>>(enc, Wpol_h, b_pol, h0, LAT_, ENC_, perm);

    // main: GRU chain, each step gated on its gi slice
    for (int t = 0; t < NMAX_; t++) {
        cudaStreamWaitEvent(0, gEv[t], 0);
        const __half* hi = (t & 1) ? h1 : h0;
        __half* ho       = (t & 1) ? h0 : h1;
        gru_step<<<dim3(16, 32), 256, G2_SMEM>>>(hi, Whp, bhp, gi, cnt_s, padoff, active, ho, t);
    }

    // main: probs (also after vnet to keep d_out writes ordered on one path)
    cudaStreamWaitEvent(0, evV, 0);
    probs_kernel<<<B_ / 8, 256>>>(h0, h1, perm, cnt_s, W_pr, b_pr, out_probs);
}

// round 16
// speedup vs baseline: 1.0276x; 1.0276x over previous
#include <cuda_runtime.h>
#include <cuda_fp16.h>
#include <cstdint>
#include <math.h>

#define B_    4096
#define OBS_  4096
#define ENC_  1024
#define LAT_  512
#define L3_   1536
#define ACT_  3
#define NMAX_ 8

// ---------------- scratch ----------------
__device__ __half g_enc[B_ * ENC_];
__device__ __half g_h0 [B_ * LAT_];
__device__ __half g_h1 [B_ * LAT_];
__device__ float  g_gi [B_ * NMAX_ * L3_];      // sliced layout: padoff[t] + sorted row
__device__ __half g_obs_h [B_ * OBS_];
__device__ __half g_nb_c  [B_ * NMAX_ * LAT_];
__device__ __half g_Wds_h [ENC_ * OBS_];
__device__ __half g_Wpol_h[LAT_ * ENC_];
__device__ __half g_Wih_h [L3_ * LAT_];
__device__ __half g_Whp   [L3_ * LAT_];
__device__ float  g_bhp   [L3_];
__device__ int    g_perm  [B_];
__device__ int    g_order [B_];
__device__ int    g_cnt_s [B_];
__device__ int    g_active[NMAX_];
__device__ int    g_padoff[NMAX_];

// ---------------- fp32 -> fp16 conversion ----------------
__global__ __launch_bounds__(256)
void to_half_k(const float* __restrict__ in, __half* __restrict__ out, int n4)
{
    int i = blockIdx.x * 256 + threadIdx.x;
    if (i >= n4) return;
    float4 v = ((const float4*)in)[i];
    ((__half2*)out)[2 * i]     = __floats2half2_rn(v.x, v.y);
    ((__half2*)out)[2 * i + 1] = __floats2half2_rn(v.z, v.w);
}

// ------- merged prep: counting sort (desc) + tables + slice offsets (1 CTA) --
__global__ __launch_bounds__(1024)
void prep_all(const int* __restrict__ counts, int* __restrict__ perm,
              int* __restrict__ order, int* __restrict__ cnt_s,
              int* __restrict__ active, int* __restrict__ padoff)
{
    __shared__ int hist[9][1024];
    const int tid = threadIdx.x;

    int c[4];
    #pragma unroll
    for (int i = 0; i < 4; i++) c[i] = counts[tid * 4 + i];
    int loc[9];
    #pragma unroll
    for (int b = 0; b < 9; b++) loc[b] = 0;
    #pragma unroll
    for (int i = 0; i < 4; i++) loc[c[i]]++;
    #pragma unroll
    for (int b = 0; b < 9; b++) hist[b][tid] = loc[b];
    __syncthreads();

    for (int o = 1; o < 1024; o <<= 1) {
        int vb[9];
        #pragma unroll
        for (int b = 0; b < 9; b++) vb[b] = (tid >= o) ? hist[b][tid - o] : 0;
        __syncthreads();
        #pragma unroll
        for (int b = 0; b < 9; b++) hist[b][tid] += vb[b];
        __syncthreads();
    }

    int total[9], start[9];
    #pragma unroll
    for (int b = 0; b < 9; b++) total[b] = hist[b][1023];
    int a = 0;
    for (int b = 8; b >= 0; b--) { start[b] = a; a += total[b]; }
    int exb[9];
    #pragma unroll
    for (int b = 0; b < 9; b++) exb[b] = hist[b][tid] - loc[b];
    #pragma unroll
    for (int i = 0; i < 4; i++) {
        int b = tid * 4 + i, cc = c[i];
        int pos = start[cc] + exb[cc]++;
        perm[b] = pos;
        order[pos] = b;
    }
    if (tid < NMAX_) active[tid] = start[tid];
    if (tid == 0) {
        int po = 0;
        #pragma unroll
        for (int t = 0; t < NMAX_; t++) {
            padoff[t] = po;
            po += ((start[t] + 127) >> 7) << 7;
        }
    }
    __syncthreads();

    #pragma unroll
    for (int i = 0; i < 4; i++) {
        int p = tid * 4 + i;
        cnt_s[p] = counts[order[p]];
    }
}

// ------- gather neighbors into sliced sorted layout + fp16 convert ----------
__global__ __launch_bounds__(256)
void gather_nb(const float* __restrict__ nb, const int* __restrict__ counts,
               const int* __restrict__ perm, const int* __restrict__ padoff,
               __half* __restrict__ out)
{
    const int b = blockIdx.x;
    const int w = threadIdx.x >> 5;
    const int lane = threadIdx.x & 31;
    if (w >= counts[b]) return;
    const float* src = nb + ((size_t)b * NMAX_ + w) * LAT_;
    __half* dst = out + (size_t)(padoff[w] + perm[b]) * LAT_;
    #pragma unroll
    for (int it = 0; it < 4; it++) {
        float4 v = *(const float4*)(src + it * 128 + lane * 4);
        *(__half2*)(dst + it * 128 + lane * 4)     = __floats2half2_rn(v.x, v.y);
        *(__half2*)(dst + it * 128 + lane * 4 + 2) = __floats2half2_rn(v.z, v.w);
    }
}

// ---------------- permute W_hh/b_hh gate-interleaved -------------
__global__ __launch_bounds__(256)
void permute_whh(const float* __restrict__ Whh, const float* __restrict__ bhh,
                 __half* __restrict__ Whp, float* __restrict__ bhp)
{
    const int m = blockIdx.x * 8 + (threadIdx.x >> 5);
    const int lane = threadIdx.x & 31;
    const int gate = m >> 9, j = m & 511;
    const int mp = ((j >> 3) * 3 + gate) * 8 + (j & 7);
    const float* src = Whh + (size_t)m * LAT_;
    __half* dst = Whp + (size_t)mp * LAT_;
    #pragma unroll
    for (int it = 0; it < 4; it++) {
        float4 v = *(const float4*)(src + it * 128 + lane * 4);
        *(__half2*)(dst + it * 128 + lane * 4)     = __floats2half2_rn(v.x, v.y);
        *(__half2*)(dst + it * 128 + lane * 4 + 2) = __floats2half2_rn(v.z, v.w);
    }
    if (lane == 0) bhp[mp] = bhh[m];
}

// ====== common MMA macros ======
#define KCH   64
#define STAGES 3

#define CP_ASYNC16(dst, src) \
    asm volatile("cp.async.cg.shared.global [%0], [%1], 16;" :: "r"(dst), "l"(src))
#define CP_COMMIT()  asm volatile("cp.async.commit_group;" ::: "memory")
#define CP_WAIT1()   asm volatile("cp.async.wait_group 1;" ::: "memory")
#define LDSM_X4(r0, r1, r2, r3, addr) \
    asm volatile("ldmatrix.sync.aligned.m8n8.x4.shared.b16 {%0,%1,%2,%3}, [%4];" \
                 : "=r"(r0), "=r"(r1), "=r"(r2), "=r"(r3) : "r"(addr))
#define HMMA16(acc, a, b) \
    asm volatile("mma.sync.aligned.m16n8k16.row.col.f32.f16.f16.f32 " \
                 "{%0, %1, %2, %3}, {%4, %5, %6, %7}, {%8, %9}, {%0, %1, %2, %3};" \
                 : "+f"((acc)[0]), "+f"((acc)[1]), "+f"((acc)[2]), "+f"((acc)[3]) \
                 : "r"((a)[0]), "r"((a)[1]), "r"((a)[2]), "r"((a)[3]), \
                   "r"((b)[0]), "r"((b)[1]))

// ====== fp16 mma.sync GEMM, BM x 128 CTA tile (enc / pol), 3-stage ======
template<int BM, int PERM>
__global__ __launch_bounds__(256, 2)
void gemm_h(const __half* __restrict__ A, const __half* __restrict__ W,
            const float* __restrict__ bias, __half* __restrict__ C,
            int N, int K, const int* __restrict__ perm)
{
    constexpr int A_TILE = BM * 144;
    constexpr int B_TILE = 128 * 144;
    constexpr int STAGE  = A_TILE + B_TILE;
    constexpr int MI     = BM / 32;

    extern __shared__ uint32_t sm[];
    const uint32_t sbase = (uint32_t)__cvta_generic_to_shared(sm);

    const int tid  = threadIdx.x;
    const int wid  = tid >> 5;
    const int lane = tid & 31;
    const int g    = lane >> 2;
    const int t    = lane & 3;
    const int wm   = wid & 1;
    const int wn   = wid >> 1;

    const int n0 = blockIdx.x * 128;
    const int m0 = blockIdx.y * BM;
    const __half* Ab = A + (size_t)m0 * K;
    const __half* Wb = W + (size_t)n0 * K;
    const int NC = K / KCH;

    const int row_ld = tid >> 3;
    const int kq_ld  = tid & 7;

    auto issue_stage = [&](int c, int s) {
        const int k0 = c * KCH;
        uint32_t a_st = sbase + (uint32_t)(s * STAGE);
        uint32_t b_st = a_st + (uint32_t)A_TILE;
        #pragma unroll
        for (int i = 0; i < BM / 32; i++) {
            int row = row_ld + i * 32;
            CP_ASYNC16(a_st + (uint32_t)(row * 144 + kq_ld * 16),
                       Ab + (size_t)row * K + k0 + kq_ld * 8);
        }
        #pragma unroll
        for (int i = 0; i < 4; i++) {
            int row = row_ld + i * 32;
            CP_ASYNC16(b_st + (uint32_t)(row * 144 + kq_ld * 16),
                       Wb + (size_t)row * K + k0 + kq_ld * 8);
        }
    };

    float acc[MI][4][4];
    #pragma unroll
    for (int i = 0; i < MI; i++)
        #pragma unroll
        for (int j = 0; j < 4; j++)
            #pragma unroll
            for (int r = 0; r < 4; r++) acc[i][j][r] = 0.f;

    issue_stage(0, 0); CP_COMMIT();
    if (NC > 1) issue_stage(1, 1);
    CP_COMMIT();

    const int lrow = lane & 15;
    const int lcol = (lane >> 4) * 16;

    for (int c = 0; c < NC; c++) {
        const int s = c % STAGES;
        CP_WAIT1();
        __syncthreads();
        if (c + 2 < NC) issue_stage(c + 2, (c + 2) % STAGES);
        CP_COMMIT();

        const uint32_t a_st = sbase + (uint32_t)(s * STAGE);
        const uint32_t b_st = a_st + (uint32_t)A_TILE;

        #pragma unroll
        for (int kk = 0; kk < 4; kk++) {
            uint32_t af[MI][4], bf[4][2];
            #pragma unroll
            for (int i = 0; i < MI; i++) {
                int row = wm * (BM / 2) + i * 16 + lrow;
                LDSM_X4(af[i][0], af[i][1], af[i][2], af[i][3],
                        a_st + (uint32_t)(row * 144 + kk * 32 + lcol));
            }
            #pragma unroll
            for (int j2 = 0; j2 < 2; j2++) {
                int row = wn * 32 + j2 * 16 + lrow;
                uint32_t r0, r1, r2, r3;
                LDSM_X4(r0, r1, r2, r3, b_st + (uint32_t)(row * 144 + kk * 32 + lcol));
                bf[j2 * 2][0] = r0; bf[j2 * 2 + 1][0] = r1;
                bf[j2 * 2][1] = r2; bf[j2 * 2 + 1][1] = r3;
            }
            #pragma unroll
            for (int i = 0; i < MI; i++)
                #pragma unroll
                for (int j = 0; j < 4; j++)
                    HMMA16(acc[i][j], af[i], bf[j]);
        }
    }

    #pragma unroll
    for (int i = 0; i < MI; i++) {
        const int row = m0 + wm * (BM / 2) + i * 16 + g;
        const int orow0 = PERM ? perm[row] : row;
        const int orow1 = PERM ? perm[row + 8] : row + 8;
        #pragma unroll
        for (int j = 0; j < 4; j++) {
            const int col = n0 + wn * 32 + j * 8 + 2 * t;
            const float b0 = bias[col], b1 = bias[col + 1];
            float x0 = fmaxf(acc[i][j][0] + b0, 0.f);
            float x1 = fmaxf(acc[i][j][1] + b1, 0.f);
            float x2 = fmaxf(acc[i][j][2] + b0, 0.f);
            float x3 = fmaxf(acc[i][j][3] + b1, 0.f);
            *(__half2*)(C + (size_t)orow0 * N + col) = __floats2half2_rn(x0, x1);
            *(__half2*)(C + (size_t)orow1 * N + col) = __floats2half2_rn(x2, x3);
        }
    }
}

#define SMEM_128 (STAGES * (128 * 144 + 128 * 144))
#define SMEM_64  (STAGES * (64 * 144 + 128 * 144))

// ====== gi slice GEMM: 3-stage (R14 config) ======
__global__ __launch_bounds__(256, 2)
void gemm_gi(const __half* __restrict__ nb, const __half* __restrict__ W,
             const float* __restrict__ bias, float* __restrict__ gi,
             const int* __restrict__ active, const int* __restrict__ padoff, int ts)
{
    const int nact = active[ts];
    if ((int)blockIdx.y * 128 >= nact) return;
    const size_t po = (size_t)padoff[ts];
    const __half* A = nb + po * LAT_;
    float* C = gi + po * L3_;
    const int K = LAT_, N = L3_;

    constexpr int STAGE = 2 * 128 * 144;
    extern __shared__ uint32_t sm[];
    const uint32_t sbase = (uint32_t)__cvta_generic_to_shared(sm);

    const int tid  = threadIdx.x;
    const int wid  = tid >> 5;
    const int lane = tid & 31;
    const int g    = lane >> 2;
    const int t    = lane & 3;
    const int wm   = wid & 1;
    const int wn   = wid >> 1;

    const int n0 = blockIdx.x * 128;
    const int m0 = blockIdx.y * 128;
    const __half* Ab = A + (size_t)m0 * K;
    const __half* Wb = W + (size_t)n0 * K;
    const int NC = K / KCH;   // 8

    const int row_ld = tid >> 3;
    const int kq_ld  = tid & 7;

    auto issue_stage = [&](int c, int s) {
        const int k0 = c * KCH;
        uint32_t a_st = sbase + (uint32_t)(s * STAGE);
        uint32_t b_st = a_st + (uint32_t)(128 * 144);
        #pragma unroll
        for (int i = 0; i < 4; i++) {
            int row = row_ld + i * 32;
            uint32_t off = (uint32_t)(row * 144 + kq_ld * 16);
            CP_ASYNC16(a_st + off, Ab + (size_t)row * K + k0 + kq_ld * 8);
            CP_ASYNC16(b_st + off, Wb + (size_t)row * K + k0 + kq_ld * 8);
        }
    };

    float acc[4][4][4];
    #pragma unroll
    for (int i = 0; i < 4; i++)
        #pragma unroll
        for (int j = 0; j < 4; j++)
            #pragma unroll
            for (int r = 0; r < 4; r++) acc[i][j][r] = 0.f;

    issue_stage(0, 0); CP_COMMIT();
    issue_stage(1, 1); CP_COMMIT();

    const int lrow = lane & 15;
    const int lcol = (lane >> 4) * 16;

    for (int c = 0; c < NC; c++) {
        const int s = c % STAGES;
        CP_WAIT1();
        __syncthreads();
        if (c + 2 < NC) issue_stage(c + 2, (c + 2) % STAGES);
        CP_COMMIT();

        const uint32_t a_st = sbase + (uint32_t)(s * STAGE);
        const uint32_t b_st = a_st + (uint32_t)(128 * 144);

        #pragma unroll
        for (int kk = 0; kk < 4; kk++) {
            uint32_t af[4][4], bf[4][2];
            #pragma unroll
            for (int i = 0; i < 4; i++) {
                int row = wm * 64 + i * 16 + lrow;
                LDSM_X4(af[i][0], af[i][1], af[i][2], af[i][3],
                        a_st + (uint32_t)(row * 144 + kk * 32 + lcol));
            }
            #pragma unroll
            for (int j2 = 0; j2 < 2; j2++) {
                int row = wn * 32 + j2 * 16 + lrow;
                uint32_t r0, r1, r2, r3;
                LDSM_X4(r0, r1, r2, r3, b_st + (uint32_t)(row * 144 + kk * 32 + lcol));
                bf[j2 * 2][0] = r0; bf[j2 * 2 + 1][0] = r1;
                bf[j2 * 2][1] = r2; bf[j2 * 2 + 1][1] = r3;
            }
            #pragma unroll
            for (int i = 0; i < 4; i++)
                #pragma unroll
                for (int j = 0; j < 4; j++)
                    HMMA16(acc[i][j], af[i], bf[j]);
        }
    }

    #pragma unroll
    for (int i = 0; i < 4; i++) {
        const int row = m0 + wm * 64 + i * 16 + g;
        #pragma unroll
        for (int j = 0; j < 4; j++) {
            const int col = n0 + wn * 32 + j * 8 + 2 * t;
            const float b0 = bias[col], b1 = bias[col + 1];
            float2 v0 = { acc[i][j][0] + b0, acc[i][j][1] + b1 };
            float2 v1 = { acc[i][j][2] + b0, acc[i][j][3] + b1 };
            *(float2*)(C + (size_t)row * N + col)       = v0;
            *(float2*)(C + (size_t)(row + 8) * N + col) = v1;
        }
    }
}

// ====== fused GRU step: 128 x 96 tile, 3-stage, 2 CTAs/SM (R14 config) ======
#define G2_AT (128 * 144)
#define G2_BT (96 * 144)
#define G2_STAGE (G2_AT + G2_BT)
#define G2_SMEM (3 * G2_STAGE)

__device__ __forceinline__ float sigmoidf_(float x) { return 1.f / (1.f + expf(-x)); }

__global__ __launch_bounds__(256, 2)
void gru_step(const __half* __restrict__ hin, const __half* __restrict__ Whp,
              const float* __restrict__ bhp, const float* __restrict__ gi,
              const int* __restrict__ cnt_s, const int* __restrict__ padoff,
              const int* __restrict__ active, __half* __restrict__ hout, int tstep)
{
    const int m0 = blockIdx.y * 128;
    const int bx = blockIdx.x;
    const int tid = threadIdx.x;
    if (m0 >= active[tstep]) return;

    extern __shared__ uint32_t sm[];
    const uint32_t sbase = (uint32_t)__cvta_generic_to_shared(sm);
    const int wid = tid >> 5, lane = tid & 31;
    const int g = lane >> 2, t4 = lane & 3;
    const int wm = wid & 3;
    const int wn = wid >> 2;

    const __half* Ab = hin + (size_t)m0 * LAT_;
    const __half* Bb = Whp + (size_t)bx * 96 * LAT_;
    const size_t po = (size_t)padoff[tstep];

    const int row_ld = tid >> 3;
    const int kq_ld  = tid & 7;

    auto issue = [&](int c, int s) {
        const int k0 = c * 64;
        uint32_t ast = sbase + (uint32_t)(s * G2_STAGE);
        uint32_t bst = ast + G2_AT;
        #pragma unroll
        for (int i = 0; i < 4; i++) {
            int row = row_ld + i * 32;
            CP_ASYNC16(ast + (uint32_t)(row * 144 + kq_ld * 16),
                       Ab + (size_t)row * LAT_ + k0 + kq_ld * 8);
        }
        #pragma unroll
        for (int i = 0; i < 3; i++) {
            int row = row_ld + i * 32;
            CP_ASYNC16(bst + (uint32_t)(row * 144 + kq_ld * 16),
                       Bb + (size_t)row * LAT_ + k0 + kq_ld * 8);
        }
    };

    float acc[2][6][4];
    #pragma unroll
    for (int i = 0; i < 2; i++)
        #pragma unroll
        for (int j = 0; j < 6; j++)
            #pragma unroll
            for (int r = 0; r < 4; r++) acc[i][j][r] = 0.f;

    issue(0, 0); CP_COMMIT();
    issue(1, 1); CP_COMMIT();

    const int lrow = lane & 15;
    const int lcol = (lane >> 4) * 16;

    for (int c = 0; c < 8; c++) {
        const int s = c % 3;
        CP_WAIT1();
        __syncthreads();
        if (c + 2 < 8) issue(c + 2, (c + 2) % 3);
        CP_COMMIT();

        const uint32_t ast = sbase + (uint32_t)(s * G2_STAGE);
        const uint32_t bst = ast + G2_AT;

        #pragma unroll
        for (int kk = 0; kk < 4; kk++) {
            uint32_t af[2][4], bf[6][2];
            #pragma unroll
            for (int i = 0; i < 2; i++) {
                int row = wm * 32 + i * 16 + lrow;
                LDSM_X4(af[i][0], af[i][1], af[i][2], af[i][3],
                        ast + (uint32_t)(row * 144 + kk * 32 + lcol));
            }
            #pragma unroll
            for (int j2 = 0; j2 < 3; j2++) {
                int row = wn * 48 + j2 * 16 + lrow;
                uint32_t r0, r1, r2, r3;
                LDSM_X4(r0, r1, r2, r3, bst + (uint32_t)(row * 144 + kk * 32 + lcol));
                bf[j2 * 2][0] = r0; bf[j2 * 2 + 1][0] = r1;
                bf[j2 * 2][1] = r2; bf[j2 * 2 + 1][1] = r3;
            }
            #pragma unroll
            for (int i = 0; i < 2; i++)
                #pragma unroll
                for (int j = 0; j < 6; j++)
                    HMMA16(acc[i][j], af[i], bf[j]);
        }
    }

    #pragma unroll
    for (int i = 0; i < 2; i++) {
        #pragma unroll
        for (int rh = 0; rh < 2; rh++) {
            const int row = m0 + wm * 32 + i * 16 + g + rh * 8;
            if (tstep >= cnt_s[row]) continue;
            const size_t girow = (po + row) * L3_;
            #pragma unroll
            for (int u = 0; u < 2; u++) {
                const int j0 = bx * 32 + (wn * 2 + u) * 8 + 2 * t4;
                const int cb = bx * 96 + wn * 48 + u * 24 + 2 * t4;
                const float ghr0 = acc[i][3*u  ][2*rh]   + bhp[cb];
                const float ghr1 = acc[i][3*u  ][2*rh+1] + bhp[cb + 1];
                const float ghz0 = acc[i][3*u+1][2*rh]   + bhp[cb + 8];
                const float ghz1 = acc[i][3*u+1][2*rh+1] + bhp[cb + 9];
                const float ghn0 = acc[i][3*u+2][2*rh]   + bhp[cb + 16];
                const float ghn1 = acc[i][3*u+2][2*rh+1] + bhp[cb + 17];
                __half2 hold = *(const __half2*)(hin + (size_t)row * LAT_ + j0);
                float h0 = __low2float(hold), h1 = __high2float(hold);
                float2 gir = *(const float2*)(gi + girow + j0);
                float2 giz = *(const float2*)(gi + girow + 512 + j0);
                float2 gin = *(const float2*)(gi + girow + 1024 + j0);
                float r0 = sigmoidf_(gir.x + ghr0);
                float r1 = sigmoidf_(gir.y + ghr1);
                float z0 = sigmoidf_(giz.x + ghz0);
                float z1 = sigmoidf_(giz.y + ghz1);
                float n0 = tanhf(gin.x + r0 * ghn0);
                float n1 = tanhf(gin.y + r1 * ghn1);
                h0 = (1.f - z0) * n0 + z0 * h0;
                h1 = (1.f - z1) * n1 + z1 * h1;
                *(__half2*)(hout + (size_t)row * LAT_ + j0) = __floats2half2_rn(h0, h1);
            }
        }
    }
}

// ---------------- value head ----------------
__global__ __launch_bounds__(256)
void vnet_kernel(const __half* __restrict__ enc, const float* __restrict__ Wv,
                 const float* __restrict__ bv, float* __restrict__ out)
{
    __shared__ float red[8];
    const int b = blockIdx.x;
    float s = 0.f;
    for (int k = threadIdx.x; k < ENC_; k += 256)
        s = fmaf(__half2float(enc[(size_t)b * ENC_ + k]), Wv[k], s);
    #pragma unroll
    for (int o = 16; o > 0; o >>= 1) s += __shfl_down_sync(0xffffffff, s, o);
    if ((threadIdx.x & 31) == 0) red[threadIdx.x >> 5] = s;
    __syncthreads();
    if (threadIdx.x == 0) {
        float tot = 0.f;
        #pragma unroll
        for (int w = 0; w < 8; w++) tot += red[w];
        out[b] = tanhf(tot + bv[0]);
    }
}

// ---------------- probs head (per-row buffer parity select) ----------------
__global__ __launch_bounds__(256)
void probs_kernel(const __half* __restrict__ h0, const __half* __restrict__ h1,
                  const int* __restrict__ perm, const int* __restrict__ cnt_s,
                  const float* __restrict__ Wpr, const float* __restrict__ bpr,
                  float* __restrict__ out)
{
    __shared__ float Ws[ACT_][LAT_];
    for (int i = threadIdx.x; i < ACT_ * LAT_; i += 256)
        Ws[i / LAT_][i % LAT_] = Wpr[i];
    __syncthreads();

    const int warp = threadIdx.x >> 5;
    const int lane = threadIdx.x & 31;
    const int b = blockIdx.x * 8 + warp;

    const int p = perm[b];
    const __half* hb = ((cnt_s[p] & 1) ? h1 : h0) + (size_t)p * LAT_;

    float a0 = 0.f, a1 = 0.f, a2 = 0.f;
    for (int k = lane; k < LAT_; k += 32) {
        float hv = __half2float(hb[k]);
        a0 = fmaf(hv, Ws[0][k], a0);
        a1 = fmaf(hv, Ws[1][k], a1);
        a2 = fmaf(hv, Ws[2][k], a2);
    }
    #pragma unroll
    for (int o = 16; o > 0; o >>= 1) {
        a0 += __shfl_down_sync(0xffffffff, a0, o);
        a1 += __shfl_down_sync(0xffffffff, a1, o);
        a2 += __shfl_down_sync(0xffffffff, a2, o);
    }
    if (lane == 0) {
        float l0 = fmaxf(a0 + bpr[0], 0.f);
        float l1 = fmaxf(a1 + bpr[1], 0.f);
        float l2 = fmaxf(a2 + bpr[2], 0.f);
        float m = fmaxf(l0, fmaxf(l1, l2));
        float e0 = expf(l0 - m), e1 = expf(l1 - m), e2 = expf(l2 - m);
        float inv = 1.f / (e0 + e1 + e2);
        out[(size_t)b * ACT_ + 0] = e0 * inv;
        out[(size_t)b * ACT_ + 1] = e1 * inv;
        out[(size_t)b * ACT_ + 2] = e2 * inv;
    }
}

// ---------------- launch ----------------
static inline void half_pass(const float* in, __half* out, size_t n, cudaStream_t s = 0) {
    int n4 = (int)(n / 4);
    to_half_k<<<(n4 + 255) / 256, 256, 0, s>>>(in, out, n4);
}

extern "C" void kernel_launch(void* const* d_in, const int* in_sizes, int n_in,
                              void* d_out, int out_size)
{
    static cudaStream_t s2 = [](){ cudaStream_t s;
        cudaStreamCreateWithFlags(&s, cudaStreamNonBlocking); return s; }();
    static cudaStream_t s3 = [](){ cudaStream_t s;
        cudaStreamCreateWithFlags(&s, cudaStreamNonBlocking); return s; }();
    static cudaEvent_t evA = [](){ cudaEvent_t e;
        cudaEventCreateWithFlags(&e, cudaEventDisableTiming); return e; }();
    static cudaEvent_t evE = [](){ cudaEvent_t e;
        cudaEventCreateWithFlags(&e, cudaEventDisableTiming); return e; }();
    static cudaEvent_t evP = [](){ cudaEvent_t e;
        cudaEventCreateWithFlags(&e, cudaEventDisableTiming); return e; }();
    static cudaEvent_t evV = [](){ cudaEvent_t e;
        cudaEventCreateWithFlags(&e, cudaEventDisableTiming); return e; }();
    static cudaEvent_t gEv[NMAX_];
    static bool evInit = [](){
        for (int i = 0; i < NMAX_; i++)
            cudaEventCreateWithFlags(&gEv[i], cudaEventDisableTiming);
        return true; }();
    (void)evInit;

    const float* observation = (const float*)d_in[0];
    const float* neighbors   = (const float*)d_in[1];
    const int*   counts      = (const int*)  d_in[2];
    const float* W_ds  = (const float*)d_in[3];
    const float* b_ds  = (const float*)d_in[4];
    const float* W_pol = (const float*)d_in[5];
    const float* b_pol = (const float*)d_in[6];
    const float* W_v   = (const float*)d_in[7];
    const float* b_v   = (const float*)d_in[8];
    const float* W_ih  = (const float*)d_in[9];
    const float* b_ih  = (const float*)d_in[10];
    const float* W_hh  = (const float*)d_in[11];
    const float* b_hh  = (const float*)d_in[12];
    const float* W_pr  = (const float*)d_in[13];
    const float* b_pr  = (const float*)d_in[14];

    float* out_probs = (float*)d_out;
    float* out_vals  = (float*)d_out + (size_t)B_ * ACT_;

    __half *enc, *h0, *h1, *obs_h, *nb_c, *Wds_h, *Wpol_h, *Wih_h, *Whp;
    float *gi, *bhp;
    int *perm, *order, *cnt_s, *active, *padoff;
    cudaGetSymbolAddress((void**)&enc,   g_enc);
    cudaGetSymbolAddress((void**)&h0,    g_h0);
    cudaGetSymbolAddress((void**)&h1,    g_h1);
    cudaGetSymbolAddress((void**)&gi,    g_gi);
    cudaGetSymbolAddress((void**)&obs_h, g_obs_h);
    cudaGetSymbolAddress((void**)&nb_c,  g_nb_c);
    cudaGetSymbolAddress((void**)&Wds_h, g_Wds_h);
    cudaGetSymbolAddress((void**)&Wpol_h,g_Wpol_h);
    cudaGetSymbolAddress((void**)&Wih_h, g_Wih_h);
    cudaGetSymbolAddress((void**)&Whp,   g_Whp);
    cudaGetSymbolAddress((void**)&bhp,   g_bhp);
    cudaGetSymbolAddress((void**)&perm,  g_perm);
    cudaGetSymbolAddress((void**)&order, g_order);
    cudaGetSymbolAddress((void**)&cnt_s, g_cnt_s);
    cudaGetSymbolAddress((void**)&active,g_active);
    cudaGetSymbolAddress((void**)&padoff,g_padoff);

    cudaFuncSetAttribute(gemm_h<128,0>, cudaFuncAttributeMaxDynamicSharedMemorySize, SMEM_128);
    cudaFuncSetAttribute(gemm_h<64,1>,  cudaFuncAttributeMaxDynamicSharedMemorySize, SMEM_64);
    cudaFuncSetAttribute(gemm_gi, cudaFuncAttributeMaxDynamicSharedMemorySize, SMEM_128);
    cudaFuncSetAttribute(gru_step, cudaFuncAttributeMaxDynamicSharedMemorySize, G2_SMEM);

    // main: enc dependencies
    half_pass(observation, obs_h, (size_t)B_ * OBS_);
    half_pass(W_ds, Wds_h, (size_t)ENC_ * OBS_);

    // fork s2 into the capture
    cudaEventRecord(evA, 0);
    cudaStreamWaitEvent(s2, evA, 0);

    // main: enc GEMM (overlaps s2 prep chain)
    gemm_h<128,0><<<dim3(ENC_ / 128, B_ / 128), 256, SMEM_128>>>(obs_h, Wds_h, b_ds, enc, ENC_, OBS_, nullptr);
    cudaEventRecord(evE, 0);

    // s3: vnet (off critical path; needs enc)
    cudaStreamWaitEvent(s3, evE, 0);
    vnet_kernel<<<B_, 256, 0, s3>>>(enc, W_v, b_v, out_vals);
    cudaEventRecord(evV, s3);

    // s2: prep chain (overlaps enc)
    prep_all<<<1, 1024, 0, s2>>>(counts, perm, order, cnt_s, active, padoff);
    gather_nb<<<B_, 256, 0, s2>>>(neighbors, counts, perm, padoff, nb_c);
    permute_whh<<<L3_ / 8, 256, 0, s2>>>(W_hh, b_hh, Whp, bhp);
    half_pass(W_ih, Wih_h, (size_t)L3_ * LAT_, s2);
    half_pass(W_pol, Wpol_h, (size_t)LAT_ * ENC_, s2);
    cudaEventRecord(evP, s2);

    // s2: gi slice GEMMs (backfill enc/pol/GRU bubbles)
    for (int t = 0; t < NMAX_; t++) {
        gemm_gi<<<dim3(L3_ / 128, 32), 256, SMEM_128, s2>>>(nb_c, Wih_h, b_ih, gi, active, padoff, t);
        cudaEventRecord(gEv[t], s2);
    }

    // main: pol (needs evP: perm, Wpol)
    cudaStreamWaitEvent(0, evP, 0);
    gemm_h<64,1><<<dim3(LAT_ / 128, B_ / 64), 256, SMEM_64>>>(enc, Wpol_h, b_pol, h0, LAT_, ENC_, perm);

    // main: GRU chain, each step gated on its gi slice
    for (int t = 0; t < NMAX_; t++) {
        cudaStreamWaitEvent(0, gEv[t], 0);
        const __half* hi = (t & 1) ? h1 : h0;
        __half* ho       = (t & 1) ? h0 : h1;
        gru_step<<<dim3(16, 32), 256, G2_SMEM>>>(hi, Whp, bhp, gi, cnt_s, padoff, active, ho, t);
    }

    // main: probs (after vnet to keep d_out writes ordered on one path)
    cudaStreamWaitEvent(0, evV, 0);
    probs_kernel<<<B_ / 8, 256>>>(h0, h1, perm, cnt_s, W_pr, b_pr, out_probs);
}